// round 6
// baseline (speedup 1.0000x reference)
#include <cuda_runtime.h>
#include <cuda_fp16.h>

// SNN: B=4096, T=256, I=7, H=64, O=8
// 1 batch/warp, 2 hidden units/lane. Recurrence fp32; output matvec per
// 32-step chunk via HMMA m16n8k16 (spikes exact fp16, W2 hi+lo split).
// R5: x staged non-duplicated padded to 8 floats/step -> per-step x read is
// 2 LDS.128 broadcasts (was 7 LDS.64); cur1 packed over input pairs.

#define THRESH 1.0f
#define BETA 0.8f

typedef unsigned long long u64;
typedef unsigned int u32;

constexpr int T_ = 256;
constexpr int I_ = 7;
constexpr int H_ = 64;
constexpr int O_ = 8;
constexpr int WPB = 4;
constexpr int TCHUNK = 32;
constexpr int SPK_STRIDE = 72;   // halves per spike row (64 + 8 pad) = 144B

__device__ __forceinline__ u64 pack2(float lo, float hi) {
    u64 r; asm("mov.b64 %0, {%1, %2};" : "=l"(r) : "f"(lo), "f"(hi)); return r;
}
__device__ __forceinline__ void unpack2(u64 v, float& lo, float& hi) {
    asm("mov.b64 {%0, %1}, %2;" : "=f"(lo), "=f"(hi) : "l"(v));
}
__device__ __forceinline__ u64 fma2(u64 a, u64 b, u64 c) {
    u64 d; asm("fma.rn.f32x2 %0, %1, %2, %3;" : "=l"(d) : "l"(a), "l"(b), "l"(c)); return d;
}
__device__ __forceinline__ u32 cvt_f16x2(float lo, float hi) {
    u32 r; asm("cvt.rn.f16x2.f32 %0, %1, %2;" : "=r"(r) : "f"(hi), "f"(lo)); return r;
}
__device__ __forceinline__ void ldsm_x4(u32& r0, u32& r1, u32& r2, u32& r3, u32 addr) {
    asm volatile("ldmatrix.sync.aligned.m8n8.x4.shared.b16 {%0,%1,%2,%3}, [%4];"
                 : "=r"(r0), "=r"(r1), "=r"(r2), "=r"(r3) : "r"(addr));
}
__device__ __forceinline__ void mma16816(float& c0, float& c1, float& c2, float& c3,
                                         u32 a0, u32 a1, u32 a2, u32 a3,
                                         u32 b0, u32 b1) {
    asm volatile("mma.sync.aligned.m16n8k16.row.col.f32.f16.f16.f32 "
                 "{%0,%1,%2,%3},{%4,%5,%6,%7},{%8,%9},{%0,%1,%2,%3};"
                 : "+f"(c0), "+f"(c1), "+f"(c2), "+f"(c3)
                 : "r"(a0), "r"(a1), "r"(a2), "r"(a3), "r"(b0), "r"(b1));
}

__global__ __launch_bounds__(WPB * 32, 7)
void snn_kernel(const float* __restrict__ x,
                const float* __restrict__ hs,
                const float* __restrict__ W1,
                const float* __restrict__ b1,
                const float* __restrict__ W2,
                const float* __restrict__ b2,
                float* __restrict__ out,     // (B,T,8)
                float* __restrict__ newh,    // (B,T,64)
                int B)
{
    // x staged plain, 8 floats (4 pairs) per timestep: u64[4] per step.
    __shared__ __align__(16) u64 xs[WPB][TCHUNK * 4];       // 4 KB
    __shared__ __align__(16) unsigned short spk[WPB][TCHUNK][SPK_STRIDE]; // 18 KB

    const int w    = threadIdx.x >> 5;
    const int lane = threadIdx.x & 31;
    const int b    = blockIdx.x * WPB + w;
    if (b >= B) return;

    const int h0 = 2 * lane;

    // --- W1 packed over input pairs for each of this lane's 2 hidden units,
    //     bias folded into the accumulator-init constant. Pad i=7 with 0. ---
    u64 w1a[4], w1b[4];
#pragma unroll
    for (int k = 0; k < 3; k++) {
        w1a[k] = pack2(W1[h0 * I_ + 2 * k],       W1[h0 * I_ + 2 * k + 1]);
        w1b[k] = pack2(W1[(h0 + 1) * I_ + 2 * k], W1[(h0 + 1) * I_ + 2 * k + 1]);
    }
    w1a[3] = pack2(W1[h0 * I_ + 6], 0.0f);
    w1b[3] = pack2(W1[(h0 + 1) * I_ + 6], 0.0f);
    const u64 b1a = pack2(b1[h0], 0.0f);
    const u64 b1b = pack2(b1[h0 + 1], 0.0f);

    // --- B fragments for HMMA (n8k16 col-major), W2 hi+lo fp16 split ---
    u32 bhi[4][2], blo[4][2];
    {
        const int o  = lane >> 2;
        const int kp = (lane & 3) * 2;
#pragma unroll
        for (int kt = 0; kt < 4; kt++) {
#pragma unroll
            for (int half = 0; half < 2; half++) {
                const int k = kt * 16 + half * 8 + kp;
                float wa = W2[o * H_ + k], wb = W2[o * H_ + k + 1];
                __half ha = __float2half_rn(wa);
                __half hb = __float2half_rn(wb);
                __half la = __float2half_rn(wa - __half2float(ha));
                __half lb = __float2half_rn(wb - __half2float(hb));
                __half2 vh = __halves2half2(ha, hb);
                __half2 vl = __halves2half2(la, lb);
                bhi[kt][half] = *reinterpret_cast<u32*>(&vh);
                blo[kt][half] = *reinterpret_cast<u32*>(&vl);
            }
        }
    }
    const float bi0 = b2[2 * (lane & 3)];
    const float bi1 = b2[2 * (lane & 3) + 1];

    // --- initial membrane + initial reset ---
    const float2 m2 = *reinterpret_cast<const float2*>(hs + (size_t)b * H_ + h0);
    float mem0 = m2.x, mem1 = m2.y;
    float s0 = (mem0 > THRESH) ? 1.0f : 0.0f;
    float s1 = (mem1 > THRESH) ? 1.0f : 0.0f;

    const float* xb = x    + (size_t)b * T_ * I_;
    float*       nh = newh + (size_t)b * T_ * H_ + h0;
    float*       ob = out  + (size_t)b * T_ * O_;

    const u32 spk_base = (u32)__cvta_generic_to_shared(&spk[w][0][0]);
    const u32 lm_addr0 = spk_base + (u32)(lane & 15) * (SPK_STRIDE * 2)
                                  + (u32)(lane >> 4) * 16;

    for (int c0 = 0; c0 < T_; c0 += TCHUNK) {
        // ---- stage x chunk: lane tt loads its timestep's 7 floats,
        //      writes 2 STS.128 (pads i=7 with 0) ----
        {
            const float* src = xb + (size_t)(c0 + lane) * I_;
            float v0 = __ldcs(src + 0), v1 = __ldcs(src + 1);
            float v2 = __ldcs(src + 2), v3 = __ldcs(src + 3);
            float v4 = __ldcs(src + 4), v5 = __ldcs(src + 5);
            float v6 = __ldcs(src + 6);
            ulonglong2 lo, hi;
            lo.x = pack2(v0, v1); lo.y = pack2(v2, v3);
            hi.x = pack2(v4, v5); hi.y = pack2(v6, 0.0f);
            *reinterpret_cast<ulonglong2*>(&xs[w][lane * 4])     = lo;
            *reinterpret_cast<ulonglong2*>(&xs[w][lane * 4 + 2]) = hi;
        }
        __syncwarp();

        // ---- phase 1: recurrence over 32 steps ----
#pragma unroll 4
        for (int tt = 0; tt < TCHUNK; tt++) {
            const int t = c0 + tt;
            // 2 LDS.128 broadcasts: the whole padded x row
            const ulonglong2 xlo = *reinterpret_cast<const ulonglong2*>(&xs[w][tt * 4]);
            const ulonglong2 xhi = *reinterpret_cast<const ulonglong2*>(&xs[w][tt * 4 + 2]);

            // cur for h0 / h1: 4 FFMA2 each, packed over input pairs
            u64 aa = fma2(xlo.x, w1a[0],
                     fma2(xlo.y, w1a[1],
                     fma2(xhi.x, w1a[2],
                     fma2(xhi.y, w1a[3], b1a))));
            u64 ab = fma2(xlo.x, w1b[0],
                     fma2(xlo.y, w1b[1],
                     fma2(xhi.x, w1b[2],
                     fma2(xhi.y, w1b[3], b1b))));
            float a0, a1, c0f, c1f;
            unpack2(aa, a0, a1); c0f = a0 + a1;
            unpack2(ab, a0, a1); c1f = a0 + a1;

            mem0 = fmaf(BETA, mem0, c0f - s0);
            mem1 = fmaf(BETA, mem1, c1f - s1);

            __stcs(reinterpret_cast<float2*>(nh + (size_t)t * H_),
                   make_float2(mem0, mem1));

            s0 = (mem0 > THRESH) ? 1.0f : 0.0f;
            s1 = (mem1 > THRESH) ? 1.0f : 0.0f;

            *reinterpret_cast<u32*>(&spk[w][tt][2 * lane]) = cvt_f16x2(s0, s1);
        }
        __syncwarp();

        // ---- phase 2: outputs for 32 steps via HMMA ----
#pragma unroll
        for (int mt = 0; mt < 2; mt++) {
            float d0 = bi0, d1 = bi1, d2 = bi0, d3 = bi1;
#pragma unroll
            for (int kt = 0; kt < 4; kt++) {
                u32 a0, a1, a2, a3;
                ldsm_x4(a0, a1, a2, a3,
                        lm_addr0 + (u32)(mt * 16 * SPK_STRIDE * 2) + (u32)(kt * 32));
                mma16816(d0, d1, d2, d3, a0, a1, a2, a3, bhi[kt][0], bhi[kt][1]);
                mma16816(d0, d1, d2, d3, a0, a1, a2, a3, blo[kt][0], blo[kt][1]);
            }
            const int row = mt * 16 + (lane >> 2);
            const int col = 2 * (lane & 3);
            __stcs(reinterpret_cast<float2*>(ob + (size_t)(c0 + row) * O_ + col),
                   make_float2(d0, d1));
            __stcs(reinterpret_cast<float2*>(ob + (size_t)(c0 + row + 8) * O_ + col),
                   make_float2(d2, d3));
        }
        __syncwarp();
    }
}

extern "C" void kernel_launch(void* const* d_in, const int* in_sizes, int n_in,
                              void* d_out, int out_size)
{
    const float* x  = (const float*)d_in[0];
    const float* hs = (const float*)d_in[1];
    const float* W1 = (const float*)d_in[2];
    const float* b1 = (const float*)d_in[3];
    const float* W2 = (const float*)d_in[4];
    const float* b2 = (const float*)d_in[5];

    const int B = in_sizes[1] / H_;

    float* out  = (float*)d_out;                       // (B,T,O)
    float* newh = (float*)d_out + (size_t)B * T_ * O_; // (B,T,H)

    const int blocks = (B + WPB - 1) / WPB;
    snn_kernel<<<blocks, WPB * 32>>>(x, hs, W1, b1, W2, b2, out, newh, B);
}

// round 7
// speedup vs baseline: 1.0034x; 1.0034x over previous
#include <cuda_runtime.h>
#include <cuda_fp16.h>

// SNN: B=4096, T=256, I=7, H=64, O=8
// 1 batch/warp, 2 hidden units/lane. Recurrence fp32; output matvec per
// 32-step chunk via HMMA m16n8k16 (spikes exact fp16, W2 hi+lo split).
// R6: launch_bounds(128,8) for 8 blocks/SM occupancy; shortened
// loop-carried chain (spike select runs parallel to the FFMA).

#define THRESH 1.0f
#define BETA 0.8f

typedef unsigned long long u64;
typedef unsigned int u32;

constexpr int T_ = 256;
constexpr int I_ = 7;
constexpr int H_ = 64;
constexpr int O_ = 8;
constexpr int WPB = 4;
constexpr int TCHUNK = 32;
constexpr int SPK_STRIDE = 72;   // halves per spike row (64 + 8 pad) = 144B

__device__ __forceinline__ u64 pack2(float lo, float hi) {
    u64 r; asm("mov.b64 %0, {%1, %2};" : "=l"(r) : "f"(lo), "f"(hi)); return r;
}
__device__ __forceinline__ void unpack2(u64 v, float& lo, float& hi) {
    asm("mov.b64 {%0, %1}, %2;" : "=f"(lo), "=f"(hi) : "l"(v));
}
__device__ __forceinline__ u64 fma2(u64 a, u64 b, u64 c) {
    u64 d; asm("fma.rn.f32x2 %0, %1, %2, %3;" : "=l"(d) : "l"(a), "l"(b), "l"(c)); return d;
}
__device__ __forceinline__ u32 cvt_f16x2(float lo, float hi) {
    u32 r; asm("cvt.rn.f16x2.f32 %0, %1, %2;" : "=r"(r) : "f"(hi), "f"(lo)); return r;
}
__device__ __forceinline__ void ldsm_x4(u32& r0, u32& r1, u32& r2, u32& r3, u32 addr) {
    asm volatile("ldmatrix.sync.aligned.m8n8.x4.shared.b16 {%0,%1,%2,%3}, [%4];"
                 : "=r"(r0), "=r"(r1), "=r"(r2), "=r"(r3) : "r"(addr));
}
__device__ __forceinline__ void mma16816(float& c0, float& c1, float& c2, float& c3,
                                         u32 a0, u32 a1, u32 a2, u32 a3,
                                         u32 b0, u32 b1) {
    asm volatile("mma.sync.aligned.m16n8k16.row.col.f32.f16.f16.f32 "
                 "{%0,%1,%2,%3},{%4,%5,%6,%7},{%8,%9},{%0,%1,%2,%3};"
                 : "+f"(c0), "+f"(c1), "+f"(c2), "+f"(c3)
                 : "r"(a0), "r"(a1), "r"(a2), "r"(a3), "r"(b0), "r"(b1));
}

__global__ __launch_bounds__(WPB * 32, 8)
void snn_kernel(const float* __restrict__ x,
                const float* __restrict__ hs,
                const float* __restrict__ W1,
                const float* __restrict__ b1,
                const float* __restrict__ W2,
                const float* __restrict__ b2,
                float* __restrict__ out,     // (B,T,8)
                float* __restrict__ newh,    // (B,T,64)
                int B)
{
    // x staged plain, 8 floats (4 pairs) per timestep: u64[4] per step.
    __shared__ __align__(16) u64 xs[WPB][TCHUNK * 4];       // 4 KB
    __shared__ __align__(16) unsigned short spk[WPB][TCHUNK][SPK_STRIDE]; // 18 KB

    const int w    = threadIdx.x >> 5;
    const int lane = threadIdx.x & 31;
    const int b    = blockIdx.x * WPB + w;
    if (b >= B) return;

    const int h0 = 2 * lane;

    // --- W1 packed over input pairs (bias folded into accumulator init) ---
    u64 w1a[4], w1b[4];
#pragma unroll
    for (int k = 0; k < 3; k++) {
        w1a[k] = pack2(W1[h0 * I_ + 2 * k],       W1[h0 * I_ + 2 * k + 1]);
        w1b[k] = pack2(W1[(h0 + 1) * I_ + 2 * k], W1[(h0 + 1) * I_ + 2 * k + 1]);
    }
    w1a[3] = pack2(W1[h0 * I_ + 6], 0.0f);
    w1b[3] = pack2(W1[(h0 + 1) * I_ + 6], 0.0f);
    const u64 b1a = pack2(b1[h0], 0.0f);
    const u64 b1b = pack2(b1[h0 + 1], 0.0f);

    // --- B fragments for HMMA (n8k16 col-major), W2 hi+lo fp16 split ---
    u32 bhi[4][2], blo[4][2];
    {
        const int o  = lane >> 2;
        const int kp = (lane & 3) * 2;
#pragma unroll
        for (int kt = 0; kt < 4; kt++) {
#pragma unroll
            for (int half = 0; half < 2; half++) {
                const int k = kt * 16 + half * 8 + kp;
                float wa = W2[o * H_ + k], wb = W2[o * H_ + k + 1];
                __half ha = __float2half_rn(wa);
                __half hb = __float2half_rn(wb);
                __half la = __float2half_rn(wa - __half2float(ha));
                __half lb = __float2half_rn(wb - __half2float(hb));
                __half2 vh = __halves2half2(ha, hb);
                __half2 vl = __halves2half2(la, lb);
                bhi[kt][half] = *reinterpret_cast<u32*>(&vh);
                blo[kt][half] = *reinterpret_cast<u32*>(&vl);
            }
        }
    }
    const float bi0 = b2[2 * (lane & 3)];
    const float bi1 = b2[2 * (lane & 3) + 1];

    // --- initial membrane + initial reset ---
    const float2 m2 = *reinterpret_cast<const float2*>(hs + (size_t)b * H_ + h0);
    float mem0 = m2.x, mem1 = m2.y;
    float s0 = (mem0 > THRESH) ? 1.0f : 0.0f;
    float s1 = (mem1 > THRESH) ? 1.0f : 0.0f;

    const float* xb = x    + (size_t)b * T_ * I_;
    float*       nh = newh + (size_t)b * T_ * H_ + h0;
    float*       ob = out  + (size_t)b * T_ * O_;

    const u32 spk_base = (u32)__cvta_generic_to_shared(&spk[w][0][0]);
    const u32 lm_addr0 = spk_base + (u32)(lane & 15) * (SPK_STRIDE * 2)
                                  + (u32)(lane >> 4) * 16;

    for (int c0 = 0; c0 < T_; c0 += TCHUNK) {
        // ---- stage x chunk: lane tt loads its timestep's 7 floats,
        //      writes 2 STS.128 (pads i=7 with 0) ----
        {
            const float* src = xb + (size_t)(c0 + lane) * I_;
            float v0 = __ldcs(src + 0), v1 = __ldcs(src + 1);
            float v2 = __ldcs(src + 2), v3 = __ldcs(src + 3);
            float v4 = __ldcs(src + 4), v5 = __ldcs(src + 5);
            float v6 = __ldcs(src + 6);
            ulonglong2 lo, hi;
            lo.x = pack2(v0, v1); lo.y = pack2(v2, v3);
            hi.x = pack2(v4, v5); hi.y = pack2(v6, 0.0f);
            *reinterpret_cast<ulonglong2*>(&xs[w][lane * 4])     = lo;
            *reinterpret_cast<ulonglong2*>(&xs[w][lane * 4 + 2]) = hi;
        }
        __syncwarp();

        // ---- phase 1: recurrence over 32 steps ----
#pragma unroll 4
        for (int tt = 0; tt < TCHUNK; tt++) {
            const int t = c0 + tt;
            // 2 LDS.128 broadcasts: the whole padded x row
            const ulonglong2 xlo = *reinterpret_cast<const ulonglong2*>(&xs[w][tt * 4]);
            const ulonglong2 xhi = *reinterpret_cast<const ulonglong2*>(&xs[w][tt * 4 + 2]);

            // cur for h0 / h1: 4 FFMA2 each, packed over input pairs
            u64 aa = fma2(xlo.x, w1a[0],
                     fma2(xlo.y, w1a[1],
                     fma2(xhi.x, w1a[2],
                     fma2(xhi.y, w1a[3], b1a))));
            u64 ab = fma2(xlo.x, w1b[0],
                     fma2(xlo.y, w1b[1],
                     fma2(xhi.x, w1b[2],
                     fma2(xhi.y, w1b[3], b1b))));
            float a0, a1, c0f, c1f;
            unpack2(aa, a0, a1); c0f = a0 + a1;
            unpack2(ab, a0, a1); c1f = a0 + a1;

            // mem' = (BETA*mem + cur) - reset : spike select runs parallel
            // to the FFMA, shortening the loop-carried chain.
            mem0 = fmaf(BETA, mem0, c0f) - s0;
            mem1 = fmaf(BETA, mem1, c1f) - s1;

            __stcs(reinterpret_cast<float2*>(nh + (size_t)t * H_),
                   make_float2(mem0, mem1));

            s0 = (mem0 > THRESH) ? 1.0f : 0.0f;
            s1 = (mem1 > THRESH) ? 1.0f : 0.0f;

            *reinterpret_cast<u32*>(&spk[w][tt][2 * lane]) = cvt_f16x2(s0, s1);
        }
        __syncwarp();

        // ---- phase 2: outputs for 32 steps via HMMA ----
#pragma unroll
        for (int mt = 0; mt < 2; mt++) {
            float d0 = bi0, d1 = bi1, d2 = bi0, d3 = bi1;
#pragma unroll
            for (int kt = 0; kt < 4; kt++) {
                u32 a0, a1, a2, a3;
                ldsm_x4(a0, a1, a2, a3,
                        lm_addr0 + (u32)(mt * 16 * SPK_STRIDE * 2) + (u32)(kt * 32));
                mma16816(d0, d1, d2, d3, a0, a1, a2, a3, bhi[kt][0], bhi[kt][1]);
                mma16816(d0, d1, d2, d3, a0, a1, a2, a3, blo[kt][0], blo[kt][1]);
            }
            const int row = mt * 16 + (lane >> 2);
            const int col = 2 * (lane & 3);
            __stcs(reinterpret_cast<float2*>(ob + (size_t)(c0 + row) * O_ + col),
                   make_float2(d0, d1));
            __stcs(reinterpret_cast<float2*>(ob + (size_t)(c0 + row + 8) * O_ + col),
                   make_float2(d2, d3));
        }
        __syncwarp();
    }
}

extern "C" void kernel_launch(void* const* d_in, const int* in_sizes, int n_in,
                              void* d_out, int out_size)
{
    const float* x  = (const float*)d_in[0];
    const float* hs = (const float*)d_in[1];
    const float* W1 = (const float*)d_in[2];
    const float* b1 = (const float*)d_in[3];
    const float* W2 = (const float*)d_in[4];
    const float* b2 = (const float*)d_in[5];

    const int B = in_sizes[1] / H_;

    float* out  = (float*)d_out;                       // (B,T,O)
    float* newh = (float*)d_out + (size_t)B * T_ * O_; // (B,T,H)

    const int blocks = (B + WPB - 1) / WPB;
    snn_kernel<<<blocks, WPB * 32>>>(x, hs, W1, b1, W2, b2, out, newh, B);
}